// round 9
// baseline (speedup 1.0000x reference)
#include <cuda_runtime.h>
#include <math.h>

// ---------------------------------------------------------------------------
// casConv2d: B=1, C=128, H=W=32, OC=128, K=3, pad=1 -> OH=OW=32, L=1024
// 36 real chunks of 32 ckk-terms; front-pad chunk is exactly zero after quant.
//
// Kernel 1: per-chunk partial sums -> g_part[l][j][oc].
//   Key change: im2col tile xcol[t][l] built ONCE per block in smem with
//   values pre-duplicated (v,v) as u64. Inner loop has only immediate
//   addresses -> no LDS->addr->LDS chains -> deep pipelining.
// Kernel 2: block-per-l reduce/quant in packed f32x2 with magic-constant
//   round-to-nearest-even (v*rcp + 1.5*2^23, exact for |v| < 2^22).
// ---------------------------------------------------------------------------

typedef unsigned long long u64;

__device__ float g_part[1024u * 36u * 128u];  // [l][j][oc]

__device__ __forceinline__ u64 fma2(u64 a, u64 b, u64 c) {
    u64 d;
    asm("fma.rn.f32x2 %0, %1, %2, %3;" : "=l"(d) : "l"(a), "l"(b), "l"(c));
    return d;
}
__device__ __forceinline__ u64 add2(u64 a, u64 b) {
    u64 d;
    asm("add.rn.f32x2 %0, %1, %2;" : "=l"(d) : "l"(a), "l"(b));
    return d;
}
__device__ __forceinline__ u64 bcast2(float v) {
    u64 d;
    unsigned u = __float_as_uint(v);
    asm("mov.b64 %0, {%1, %1};" : "=l"(d) : "r"(u));
    return d;
}
__device__ __forceinline__ float2 unpack2(u64 v) {
    float2 f;
    asm("mov.b64 {%0, %1}, %2;" : "=f"(f.x), "=f"(f.y) : "l"(v));
    return f;
}
__device__ __forceinline__ u64 pack2(float x, float y) {
    u64 d;
    asm("mov.b64 %0, {%1, %2};" : "=l"(d) : "f"(x), "f"(y));
    return d;
}

// ---------------------------------------------------------------------------
// Kernel 1: grid (16 l-tiles, 36 chunks), block 256.
// Block tile: 128 oc x 64 l (2 rows x 32 cols); thread tile 8 oc x 4 l.
// xcol layout: [t][slot], slot = i*16 + q, where thread q (=tid&15) computes
// l = lrow*32 + c4*4 + i  (lrow=q>>3, c4=q&7).  Inner x read: 16 consecutive
// u64 per i -> conflict-free; w read: broadcast quads, stride-130 pad.
// ---------------------------------------------------------------------------
__global__ void __launch_bounds__(256)
k_partials(const float* __restrict__ x, const float* __restrict__ w) {
    __shared__ float xraw[5 * 4 * 34];    // [c_rel][row(4)][col(34)], zero halo
    __shared__ int   xoff_s[32];
    __shared__ u64   xcol[32 * 64];       // [t][i*16+q], (v,v) duplicated
    __shared__ float w_s[32 * 130];       // [m][oc], stride 130 (2-way STS)

    const int j    = blockIdx.y;
    const int oh0  = blockIdx.x * 2;
    const int base = 32 * j;
    const int cmin = base / 9;
    const int r0   = base - 9 * cmin;
    const int tid  = threadIdx.x;

    if (tid < 32) {
        int idx9 = r0 + tid;
        int cr   = idx9 / 9;
        int rem  = idx9 - cr * 9;
        int kh   = rem / 3;
        int kw   = rem - kh * 3;
        xoff_s[tid] = cr * 136 + kh * 34 + kw;
    }
    for (int e = tid; e < 5 * 4 * 34; e += 256) {
        int cr  = e / 136;
        int rem = e - cr * 136;
        int rr  = rem / 34;
        int cc  = rem - rr * 34;
        int c   = cmin + cr;
        int gh  = oh0 - 1 + rr;
        int gw  = cc - 1;
        float v = 0.0f;
        if (c < 128 && (unsigned)gh < 32u && (unsigned)gw < 32u)
            v = x[(c << 10) + (gh << 5) + gw];
        xraw[e] = v;
    }
    for (int e = tid; e < 4096; e += 256) {
        int oc = e >> 5;
        int m  = e & 31;
        w_s[m * 130 + oc] = w[oc * 1152 + base + m];
    }
    __syncthreads();

    // build xcol: 2048 entries, 8 per thread
#pragma unroll
    for (int k = 0; k < 8; ++k) {
        int e    = tid + k * 256;
        int t    = e >> 6;
        int slot = e & 63;
        int i    = slot >> 4;
        int q    = slot & 15;
        int lrow = q >> 3;
        int c4   = q & 7;
        float v  = xraw[xoff_s[t] + lrow * 34 + c4 * 4 + i];
        unsigned uv = __float_as_uint(v);
        xcol[e] = ((u64)uv << 32) | uv;
    }
    __syncthreads();

    const int q   = tid & 15;
    const int oc0 = (tid >> 4) << 3;
    const u64* xb = xcol + q;
    const u64* wb = (const u64*)w_s + (oc0 >> 1);

    u64 acc[4][4] = {};                   // [oc-pair][i]
#pragma unroll
    for (int t = 0; t < 32; ++t) {
        const u64 x0 = xb[t * 64 +  0];
        const u64 x1 = xb[t * 64 + 16];
        const u64 x2 = xb[t * 64 + 32];
        const u64 x3 = xb[t * 64 + 48];
        const u64 w0 = wb[t * 65 + 0];
        const u64 w1 = wb[t * 65 + 1];
        const u64 w2 = wb[t * 65 + 2];
        const u64 w3 = wb[t * 65 + 3];
        acc[0][0] = fma2(w0, x0, acc[0][0]);
        acc[1][0] = fma2(w1, x0, acc[1][0]);
        acc[2][0] = fma2(w2, x0, acc[2][0]);
        acc[3][0] = fma2(w3, x0, acc[3][0]);
        acc[0][1] = fma2(w0, x1, acc[0][1]);
        acc[1][1] = fma2(w1, x1, acc[1][1]);
        acc[2][1] = fma2(w2, x1, acc[2][1]);
        acc[3][1] = fma2(w3, x1, acc[3][1]);
        acc[0][2] = fma2(w0, x2, acc[0][2]);
        acc[1][2] = fma2(w1, x2, acc[1][2]);
        acc[2][2] = fma2(w2, x2, acc[2][2]);
        acc[3][2] = fma2(w3, x2, acc[3][2]);
        acc[0][3] = fma2(w0, x3, acc[0][3]);
        acc[1][3] = fma2(w1, x3, acc[1][3]);
        acc[2][3] = fma2(w2, x3, acc[2][3]);
        acc[3][3] = fma2(w3, x3, acc[3][3]);
    }

    // store: l = (oh0 + lrow)*32 + c4*4 + i
    const int lrow = q >> 3;
    const int c4   = q & 7;
    const int lbase = (oh0 + lrow) * 32 + (c4 << 2);
    float* outp = g_part + (size_t)(j << 7) + oc0;
#pragma unroll
    for (int i = 0; i < 4; ++i) {
        float2 a0 = unpack2(acc[0][i]);
        float2 a1 = unpack2(acc[1][i]);
        float2 a2 = unpack2(acc[2][i]);
        float2 a3 = unpack2(acc[3][i]);
        float* po = outp + (size_t)(lbase + i) * 4608;
        *(float4*)(po)     = make_float4(a0.x, a0.y, a1.x, a1.y);
        *(float4*)(po + 4) = make_float4(a2.x, a2.y, a3.x, a3.y);
    }
}

// ---------------------------------------------------------------------------
// Kernel 2: block (128 thr, 4 warps) per l; grid = 1024.
// Warp w: chunks [9w, 9w+9); lane: oc quad lane*4..+3 (one LDG.128/chunk).
// Packed f32x2 math; RNE via magic constant 1.5*2^23 (exact, |v| << 2^22).
// ---------------------------------------------------------------------------
__global__ void __launch_bounds__(128)
k_quant(const float* __restrict__ bias, float* __restrict__ out) {
    const int tid  = threadIdx.x;
    const int lane = tid & 31;
    const int wid  = tid >> 5;
    const int l    = blockIdx.x;
    const int j0   = wid * 9;

    const longlong2* bp =
        (const longlong2*)(g_part + (size_t)l * 4608) + lane;
    // chunk j at bp[j*32]  (128 floats = 32 longlong2 per chunk)

    __shared__ longlong2 s[4][32];

    // single load: 9 chunks; packed partial totals
    longlong2 pv[9];
    u64 t0 = 0ull, t1 = 0ull;                        // (+0.0, +0.0) pairs
#pragma unroll
    for (int j = 0; j < 9; ++j) {
        pv[j] = bp[(j0 + j) * 32];
        t0 = add2(t0, (u64)pv[j].x);
        t1 = add2(t1, (u64)pv[j].y);
    }
    s[wid][lane] = make_longlong2((long long)t0, (long long)t1);
    __syncthreads();

    // full totals (+bias), redundantly in every warp
    longlong2 bb = ((const longlong2*)bias)[lane];
    u64 tot0 = (u64)bb.x, tot1 = (u64)bb.y;
#pragma unroll
    for (int w2 = 0; w2 < 4; ++w2) {
        longlong2 v = s[w2][lane];
        tot0 = add2(tot0, (u64)v.x);
        tot1 = add2(tot1, (u64)v.y);
    }
    float2 f0 = unpack2(tot0), f1 = unpack2(tot1);
    float mx = fmaxf(fmaxf(f0.x, f0.y), fmaxf(f1.x, f1.y));
    float mn = fminf(fminf(f0.x, f0.y), fminf(f1.x, f1.y));
#pragma unroll
    for (int sft = 16; sft > 0; sft >>= 1) {
        mx = fmaxf(mx, __shfl_xor_sync(0xffffffffu, mx, sft));
        mn = fminf(mn, __shfl_xor_sync(0xffffffffu, mn, sft));
    }

    const float sc = (mx - mn) * (1.0f / 255.0f);
    float z = -mn / sc;                              // inf/nan if sc==0
    z = fminf(fmaxf(z, 0.0f), 255.0f);               // clip (nan -> 0)
    if (isnan(z)) z = 0.0f;
    const float zp  = truncf(z);                     // .int() truncation
    const float rcp = 1.0f / sc;

    const float MAGIC = 12582912.0f;                 // 1.5 * 2^23
    const u64 rcp2 = bcast2(rcp);
    const u64 mg2  = bcast2(MAGIC);
    const u64 zm2  = bcast2(zp - MAGIC);

    // quant from registers: q_clip accumulated; zp folded out at the end
    float ox = 0.f, oy = 0.f, oz = 0.f, ow = 0.f;
#pragma unroll
    for (int j = 0; j < 9; ++j) {
        u64 r0 = add2(fma2((u64)pv[j].x, rcp2, mg2), zm2);  // rint(v/sc)+zp
        u64 r1 = add2(fma2((u64)pv[j].y, rcp2, mg2), zm2);
        float2 c0 = unpack2(r0), c1 = unpack2(r1);
        ox += fminf(fmaxf(c0.x, 0.0f), 255.0f);
        oy += fminf(fmaxf(c0.y, 0.0f), 255.0f);
        oz += fminf(fmaxf(c1.x, 0.0f), 255.0f);
        ow += fminf(fmaxf(c1.y, 0.0f), 255.0f);
    }
    __syncthreads();
    s[wid][lane] = make_longlong2((long long)pack2(ox, oy),
                                  (long long)pack2(oz, ow));
    __syncthreads();

    // combine warps; output = (sum_q - 36*zp) * sc ; thread tid <-> oc
    const float* sf = (const float*)s;               // [warp][128 oc]
    float v = sf[tid] + sf[128 + tid] + sf[256 + tid] + sf[384 + tid];
    out[(tid << 10) + l] = (v - 36.0f * zp) * sc;
}

// ---------------------------------------------------------------------------
extern "C" void kernel_launch(void* const* d_in, const int* in_sizes, int n_in,
                              void* d_out, int out_size) {
    const float *x = nullptr, *w = nullptr, *b = nullptr;
    for (int i = 0; i < n_in; ++i) {
        if      (in_sizes[i] == 131072) x = (const float*)d_in[i];  // 128*32*32
        else if (in_sizes[i] == 147456) w = (const float*)d_in[i];  // 128*128*9
        else if (in_sizes[i] == 128)    b = (const float*)d_in[i];
    }
    k_partials<<<dim3(16, 36), 256>>>(x, w);
    k_quant<<<1024, 128>>>(b, (float*)d_out);
}

// round 10
// speedup vs baseline: 1.3205x; 1.3205x over previous
#include <cuda_runtime.h>
#include <math.h>

// ---------------------------------------------------------------------------
// casConv2d: B=1, C=128, H=W=32, OC=128, K=3, pad=1 -> OH=OW=32, L=1024
// 36 real chunks of 32 ckk-terms; front-pad chunk is exactly zero after quant.
//
// Kernel 1 v4: tile 16oc x 4l per thread (32 f32x2 accs), 2 blocks/SM.
//   All smem accesses bank-conflict-free by construction:
//   - w_s[m][coff(oc)] with coff = (P>>3)*16 + (P&7)*2 + h  (P=oc>>1, h=oc&1)
//     -> reader's 8 LDS.64/t are consecutive u64 (distinct bank pairs),
//        writer's scalar STS land on banks 0..31 exactly.
//   - xraw row stride 35 -> the 4 row-classes occupy distinct mod-4 banks.
//   FFMA2:other = 32:14 per t -> fma-pipe-bound (floor ~4us).
// Kernel 2: block-per-l reduce/quant in packed f32x2 (R9 version).
// ---------------------------------------------------------------------------

typedef unsigned long long u64;

__device__ float g_part[1024u * 36u * 128u];  // [l][j][oc]

__device__ __forceinline__ u64 fma2(u64 a, u64 b, u64 c) {
    u64 d;
    asm("fma.rn.f32x2 %0, %1, %2, %3;" : "=l"(d) : "l"(a), "l"(b), "l"(c));
    return d;
}
__device__ __forceinline__ u64 add2(u64 a, u64 b) {
    u64 d;
    asm("add.rn.f32x2 %0, %1, %2;" : "=l"(d) : "l"(a), "l"(b));
    return d;
}
__device__ __forceinline__ u64 bcast2(float v) {
    u64 d;
    unsigned u = __float_as_uint(v);
    asm("mov.b64 %0, {%1, %1};" : "=l"(d) : "r"(u));
    return d;
}
__device__ __forceinline__ float2 unpack2(u64 v) {
    float2 f;
    asm("mov.b64 {%0, %1}, %2;" : "=f"(f.x), "=f"(f.y) : "l"(v));
    return f;
}
__device__ __forceinline__ u64 pack2(float x, float y) {
    u64 d;
    asm("mov.b64 %0, {%1, %2};" : "=l"(d) : "f"(x), "f"(y));
    return d;
}

// ---------------------------------------------------------------------------
// Kernel 1: grid (8 l-tiles, 36 chunks), block 256, 2 blocks/SM.
// Block tile: 128 oc x 128 l (4 rows x 32 cols); thread: 16 oc x 4 l.
// tid = lgrp*8 + ocg:  ocg in 0..7 (owns oc pairs P = p*8+ocg, p=0..7),
//                      lgrp in 0..31 (row = lgrp>>3, colb = (lgrp&7)*4).
// ---------------------------------------------------------------------------
__global__ void __launch_bounds__(256, 2)
k_partials(const float* __restrict__ x, const float* __restrict__ w) {
    __shared__ float xraw[5 * 6 * 35];    // [c_rel][row(6)][col], stride 35
    __shared__ float w_s[32 * 130];       // [m][coff(oc)], stride 130
    __shared__ int   xoff_s[32];

    const int j    = blockIdx.y;
    const int oh0  = blockIdx.x * 4;      // 4 output rows per block
    const int base = 32 * j;
    const int cmin = base / 9;
    const int r0   = base - 9 * cmin;
    const int tid  = threadIdx.x;

    if (tid < 32) {
        int idx9 = r0 + tid;
        int cr   = idx9 / 9;
        int rem  = idx9 - cr * 9;
        int kh   = rem / 3;
        int kw   = rem - kh * 3;
        xoff_s[tid] = cr * 210 + kh * 35 + kw;
    }

    // x halo: channels cmin..cmin+4, rows oh0-1..oh0+4, cols -1..32 (stride 35)
    for (int e = tid; e < 5 * 6 * 35; e += 256) {
        int cr  = e / 210;
        int rem = e - cr * 210;
        int rr  = rem / 35;
        int cc  = rem - rr * 35;
        int c   = cmin + cr;
        int gh  = oh0 - 1 + rr;
        int gw  = cc - 1;
        float v = 0.0f;
        if (cc < 34 && c < 128 && (unsigned)gh < 32u && (unsigned)gw < 32u)
            v = x[(c << 10) + (gh << 5) + gw];
        xraw[e] = v;
    }

    // w: thread (oc = tid&127, half = tid>>7) loads 16 consecutive floats of
    // its oc's chunk row as 4x LDG.128, stores with the coff permutation.
    {
        const int oc   = tid & 127;
        const int half = tid >> 7;
        const int P    = oc >> 1;
        const int coff = ((P >> 3) << 4) + ((P & 7) << 1) + (oc & 1);
        const float4* src =
            (const float4*)(w + oc * 1152 + base + half * 16);
        float4 v0 = src[0], v1 = src[1], v2 = src[2], v3 = src[3];
        float* dst = w_s + half * 16 * 130 + coff;
        dst[0 * 130] = v0.x; dst[1 * 130] = v0.y;
        dst[2 * 130] = v0.z; dst[3 * 130] = v0.w;
        dst[4 * 130] = v1.x; dst[5 * 130] = v1.y;
        dst[6 * 130] = v1.z; dst[7 * 130] = v1.w;
        dst[8 * 130] = v2.x; dst[9 * 130] = v2.y;
        dst[10 * 130] = v2.z; dst[11 * 130] = v2.w;
        dst[12 * 130] = v3.x; dst[13 * 130] = v3.y;
        dst[14 * 130] = v3.z; dst[15 * 130] = v3.w;
    }
    __syncthreads();

    const int ocg  = tid & 7;
    const int lgrp = tid >> 3;
    const int row  = lgrp >> 3;           // 0..3
    const int colb = (lgrp & 7) << 2;     // 0..28
    const float* xb = xraw + row * 35 + colb;
    const u64*   wb = (const u64*)w_s + ocg;   // + t*65 + p*8

    u64 acc[8][4] = {};                   // [p][i], oc pair P = p*8 + ocg
#pragma unroll
    for (int t = 0; t < 32; ++t) {
        const float* xr = xb + xoff_s[t];
        const u64 x0 = bcast2(xr[0]);
        const u64 x1 = bcast2(xr[1]);
        const u64 x2 = bcast2(xr[2]);
        const u64 x3 = bcast2(xr[3]);
        const u64* wq = wb + t * 65;
#pragma unroll
        for (int p = 0; p < 8; ++p) {
            const u64 wv = wq[p * 8];
            acc[p][0] = fma2(wv, x0, acc[p][0]);
            acc[p][1] = fma2(wv, x1, acc[p][1]);
            acc[p][2] = fma2(wv, x2, acc[p][2]);
            acc[p][3] = fma2(wv, x3, acc[p][3]);
        }
    }

    // store: l = (oh0+row)*32 + colb + i ; acc[p] -> oc = 16p + 2*ocg
    const int lbase = ((oh0 + row) << 5) + colb;
#pragma unroll
    for (int i = 0; i < 4; ++i) {
        float* po = g_part + (size_t)(lbase + i) * 4608 + (j << 7) + (ocg << 1);
#pragma unroll
        for (int p = 0; p < 8; ++p) {
            float2 f = unpack2(acc[p][i]);
            *(float2*)(po + (p << 4)) = f;
        }
    }
}

// ---------------------------------------------------------------------------
// Kernel 2: block (128 thr, 4 warps) per l; grid = 1024.  (R9 version)
// ---------------------------------------------------------------------------
__global__ void __launch_bounds__(128)
k_quant(const float* __restrict__ bias, float* __restrict__ out) {
    const int tid  = threadIdx.x;
    const int lane = tid & 31;
    const int wid  = tid >> 5;
    const int l    = blockIdx.x;
    const int j0   = wid * 9;

    const longlong2* bp =
        (const longlong2*)(g_part + (size_t)l * 4608) + lane;

    __shared__ longlong2 s[4][32];

    longlong2 pv[9];
    u64 t0 = 0ull, t1 = 0ull;
#pragma unroll
    for (int j = 0; j < 9; ++j) {
        pv[j] = bp[(j0 + j) * 32];
        t0 = add2(t0, (u64)pv[j].x);
        t1 = add2(t1, (u64)pv[j].y);
    }
    s[wid][lane] = make_longlong2((long long)t0, (long long)t1);
    __syncthreads();

    longlong2 bb = ((const longlong2*)bias)[lane];
    u64 tot0 = (u64)bb.x, tot1 = (u64)bb.y;
#pragma unroll
    for (int w2 = 0; w2 < 4; ++w2) {
        longlong2 v = s[w2][lane];
        tot0 = add2(tot0, (u64)v.x);
        tot1 = add2(tot1, (u64)v.y);
    }
    float2 f0 = unpack2(tot0), f1 = unpack2(tot1);
    float mx = fmaxf(fmaxf(f0.x, f0.y), fmaxf(f1.x, f1.y));
    float mn = fminf(fminf(f0.x, f0.y), fminf(f1.x, f1.y));
#pragma unroll
    for (int sft = 16; sft > 0; sft >>= 1) {
        mx = fmaxf(mx, __shfl_xor_sync(0xffffffffu, mx, sft));
        mn = fminf(mn, __shfl_xor_sync(0xffffffffu, mn, sft));
    }

    const float sc = (mx - mn) * (1.0f / 255.0f);
    float z = -mn / sc;                              // inf/nan if sc==0
    z = fminf(fmaxf(z, 0.0f), 255.0f);               // clip (nan -> 0)
    if (isnan(z)) z = 0.0f;
    const float zp  = truncf(z);                     // .int() truncation
    const float rcp = 1.0f / sc;

    const float MAGIC = 12582912.0f;                 // 1.5 * 2^23
    const u64 rcp2 = bcast2(rcp);
    const u64 mg2  = bcast2(MAGIC);
    const u64 zm2  = bcast2(zp - MAGIC);

    float ox = 0.f, oy = 0.f, oz = 0.f, ow = 0.f;
#pragma unroll
    for (int j = 0; j < 9; ++j) {
        u64 r0 = add2(fma2((u64)pv[j].x, rcp2, mg2), zm2);  // rint(v/sc)+zp
        u64 r1 = add2(fma2((u64)pv[j].y, rcp2, mg2), zm2);
        float2 c0 = unpack2(r0), c1 = unpack2(r1);
        ox += fminf(fmaxf(c0.x, 0.0f), 255.0f);
        oy += fminf(fmaxf(c0.y, 0.0f), 255.0f);
        oz += fminf(fmaxf(c1.x, 0.0f), 255.0f);
        ow += fminf(fmaxf(c1.y, 0.0f), 255.0f);
    }
    __syncthreads();
    s[wid][lane] = make_longlong2((long long)pack2(ox, oy),
                                  (long long)pack2(oz, ow));
    __syncthreads();

    const float* sf = (const float*)s;               // [warp][128 oc]
    float v = sf[tid] + sf[128 + tid] + sf[256 + tid] + sf[384 + tid];
    out[(tid << 10) + l] = (v - 36.0f * zp) * sc;
}

// ---------------------------------------------------------------------------
extern "C" void kernel_launch(void* const* d_in, const int* in_sizes, int n_in,
                              void* d_out, int out_size) {
    const float *x = nullptr, *w = nullptr, *b = nullptr;
    for (int i = 0; i < n_in; ++i) {
        if      (in_sizes[i] == 131072) x = (const float*)d_in[i];  // 128*32*32
        else if (in_sizes[i] == 147456) w = (const float*)d_in[i];  // 128*128*9
        else if (in_sizes[i] == 128)    b = (const float*)d_in[i];
    }
    k_partials<<<dim3(8, 36), 256>>>(x, w);
    k_quant<<<1024, 128>>>(b, (float*)d_out);
}

// round 11
// speedup vs baseline: 1.3384x; 1.0135x over previous
#include <cuda_runtime.h>
#include <math.h>

// ---------------------------------------------------------------------------
// casConv2d: B=1, C=128, H=W=32, OC=128, K=3, pad=1 -> OH=OW=32, L=1024
// 36 real chunks of 32 ckk-terms; front-pad chunk is exactly zero after quant.
//
// Kernel 1 v5: tile 16oc x 4l per thread (32 f32x2 accs), 2 blocks/SM.
//   - x halo stored as DUPLICATED (v,v) u64 -> x operand is one LDS.64,
//     no mov.b64 broadcast in the inner loop.
//   - per t: 4 LDS.64(x) + 8 LDS.64(w) + 32 FFMA2, operands staged in regs
//     before the FMA burst so ptxas pipelines loads across t.
//   - w_s[m][coff(oc)] permutation: conflict-free STS and LDS.
// Kernel 2: block-per-l reduce/quant in packed f32x2 (R9 version).
// ---------------------------------------------------------------------------

typedef unsigned long long u64;

__device__ float g_part[1024u * 36u * 128u];  // [l][j][oc]

__device__ __forceinline__ u64 fma2(u64 a, u64 b, u64 c) {
    u64 d;
    asm("fma.rn.f32x2 %0, %1, %2, %3;" : "=l"(d) : "l"(a), "l"(b), "l"(c));
    return d;
}
__device__ __forceinline__ u64 add2(u64 a, u64 b) {
    u64 d;
    asm("add.rn.f32x2 %0, %1, %2;" : "=l"(d) : "l"(a), "l"(b));
    return d;
}
__device__ __forceinline__ u64 bcast2(float v) {
    u64 d;
    unsigned u = __float_as_uint(v);
    asm("mov.b64 %0, {%1, %1};" : "=l"(d) : "r"(u));
    return d;
}
__device__ __forceinline__ float2 unpack2(u64 v) {
    float2 f;
    asm("mov.b64 {%0, %1}, %2;" : "=f"(f.x), "=f"(f.y) : "l"(v));
    return f;
}
__device__ __forceinline__ u64 pack2(float x, float y) {
    u64 d;
    asm("mov.b64 %0, {%1, %2};" : "=l"(d) : "f"(x), "f"(y));
    return d;
}

// ---------------------------------------------------------------------------
// Kernel 1: grid (8 l-tiles, 36 chunks), block 256, 2 blocks/SM.
// Block tile: 128 oc x 128 l (4 rows x 32 cols); thread: 16 oc x 4 l.
// tid = lgrp*8 + ocg:  ocg 0..7 (oc pairs P = p*8+ocg, p=0..7),
//                      lgrp 0..31 (row = lgrp>>3, colb = (lgrp&7)*4).
// ---------------------------------------------------------------------------
__global__ void __launch_bounds__(256, 2)
k_partials(const float* __restrict__ x, const float* __restrict__ w) {
    __shared__ u64   xdup[5 * 6 * 35];    // [c_rel][row(6)][col(35)], (v,v)
    __shared__ float w_s[32 * 130];       // [m][coff(oc)], stride 130
    __shared__ int   xoff_s[32];          // u64-element offsets

    const int j    = blockIdx.y;
    const int oh0  = blockIdx.x * 4;      // 4 output rows per block
    const int base = 32 * j;
    const int cmin = base / 9;
    const int r0   = base - 9 * cmin;
    const int tid  = threadIdx.x;

    if (tid < 32) {
        int idx9 = r0 + tid;
        int cr   = idx9 / 9;
        int rem  = idx9 - cr * 9;
        int kh   = rem / 3;
        int kw   = rem - kh * 3;
        xoff_s[tid] = cr * 210 + kh * 35 + kw;
    }

    // x halo: channels cmin..cmin+4, rows oh0-1..oh0+4, cols -1..32, (v,v) dup
    for (int e = tid; e < 5 * 6 * 35; e += 256) {
        int cr  = e / 210;
        int rem = e - cr * 210;
        int rr  = rem / 35;
        int cc  = rem - rr * 35;
        int c   = cmin + cr;
        int gh  = oh0 - 1 + rr;
        int gw  = cc - 1;
        float v = 0.0f;
        if (cc < 34 && c < 128 && (unsigned)gh < 32u && (unsigned)gw < 32u)
            v = x[(c << 10) + (gh << 5) + gw];
        unsigned uv = __float_as_uint(v);
        xdup[e] = ((u64)uv << 32) | uv;
    }

    // w: thread (oc = tid&127, half = tid>>7) loads 16 floats of its oc's
    // chunk row as 4x LDG.128, stores via the coff permutation (bank-clean).
    {
        const int oc   = tid & 127;
        const int half = tid >> 7;
        const int P    = oc >> 1;
        const int coff = ((P >> 3) << 4) + ((P & 7) << 1) + (oc & 1);
        const float4* src =
            (const float4*)(w + oc * 1152 + base + half * 16);
        float4 v0 = src[0], v1 = src[1], v2 = src[2], v3 = src[3];
        float* dst = w_s + half * 16 * 130 + coff;
        dst[0 * 130] = v0.x; dst[1 * 130] = v0.y;
        dst[2 * 130] = v0.z; dst[3 * 130] = v0.w;
        dst[4 * 130] = v1.x; dst[5 * 130] = v1.y;
        dst[6 * 130] = v1.z; dst[7 * 130] = v1.w;
        dst[8 * 130] = v2.x; dst[9 * 130] = v2.y;
        dst[10 * 130] = v2.z; dst[11 * 130] = v2.w;
        dst[12 * 130] = v3.x; dst[13 * 130] = v3.y;
        dst[14 * 130] = v3.z; dst[15 * 130] = v3.w;
    }
    __syncthreads();

    const int ocg  = tid & 7;
    const int lgrp = tid >> 3;
    const int row  = lgrp >> 3;           // 0..3
    const int colb = (lgrp & 7) << 2;     // 0..28
    const u64* xb = xdup + row * 35 + colb;
    const u64* wb = (const u64*)w_s + ocg;   // + t*65 + p*8

    u64 acc[8][4] = {};                   // [p][i], oc pair P = p*8 + ocg
#pragma unroll
    for (int t = 0; t < 32; ++t) {
        const u64* xr = xb + xoff_s[t];
        // stage all operands first -> clean load block / FMA block per t
        const u64 x0 = xr[0];
        const u64 x1 = xr[1];
        const u64 x2 = xr[2];
        const u64 x3 = xr[3];
        const u64* wq = wb + t * 65;
        const u64 wv0 = wq[0 * 8];
        const u64 wv1 = wq[1 * 8];
        const u64 wv2 = wq[2 * 8];
        const u64 wv3 = wq[3 * 8];
        const u64 wv4 = wq[4 * 8];
        const u64 wv5 = wq[5 * 8];
        const u64 wv6 = wq[6 * 8];
        const u64 wv7 = wq[7 * 8];
        acc[0][0] = fma2(wv0, x0, acc[0][0]);
        acc[0][1] = fma2(wv0, x1, acc[0][1]);
        acc[0][2] = fma2(wv0, x2, acc[0][2]);
        acc[0][3] = fma2(wv0, x3, acc[0][3]);
        acc[1][0] = fma2(wv1, x0, acc[1][0]);
        acc[1][1] = fma2(wv1, x1, acc[1][1]);
        acc[1][2] = fma2(wv1, x2, acc[1][2]);
        acc[1][3] = fma2(wv1, x3, acc[1][3]);
        acc[2][0] = fma2(wv2, x0, acc[2][0]);
        acc[2][1] = fma2(wv2, x1, acc[2][1]);
        acc[2][2] = fma2(wv2, x2, acc[2][2]);
        acc[2][3] = fma2(wv2, x3, acc[2][3]);
        acc[3][0] = fma2(wv3, x0, acc[3][0]);
        acc[3][1] = fma2(wv3, x1, acc[3][1]);
        acc[3][2] = fma2(wv3, x2, acc[3][2]);
        acc[3][3] = fma2(wv3, x3, acc[3][3]);
        acc[4][0] = fma2(wv4, x0, acc[4][0]);
        acc[4][1] = fma2(wv4, x1, acc[4][1]);
        acc[4][2] = fma2(wv4, x2, acc[4][2]);
        acc[4][3] = fma2(wv4, x3, acc[4][3]);
        acc[5][0] = fma2(wv5, x0, acc[5][0]);
        acc[5][1] = fma2(wv5, x1, acc[5][1]);
        acc[5][2] = fma2(wv5, x2, acc[5][2]);
        acc[5][3] = fma2(wv5, x3, acc[5][3]);
        acc[6][0] = fma2(wv6, x0, acc[6][0]);
        acc[6][1] = fma2(wv6, x1, acc[6][1]);
        acc[6][2] = fma2(wv6, x2, acc[6][2]);
        acc[6][3] = fma2(wv6, x3, acc[6][3]);
        acc[7][0] = fma2(wv7, x0, acc[7][0]);
        acc[7][1] = fma2(wv7, x1, acc[7][1]);
        acc[7][2] = fma2(wv7, x2, acc[7][2]);
        acc[7][3] = fma2(wv7, x3, acc[7][3]);
    }

    // store: l = (oh0+row)*32 + colb + i ; acc[p] -> oc = 16p + 2*ocg
    const int lbase = ((oh0 + row) << 5) + colb;
#pragma unroll
    for (int i = 0; i < 4; ++i) {
        float* po = g_part + (size_t)(lbase + i) * 4608 + (j << 7) + (ocg << 1);
#pragma unroll
        for (int p = 0; p < 8; ++p) {
            float2 f = unpack2(acc[p][i]);
            *(float2*)(po + (p << 4)) = f;
        }
    }
}

// ---------------------------------------------------------------------------
// Kernel 2: block (128 thr, 4 warps) per l; grid = 1024.  (R9 version)
// ---------------------------------------------------------------------------
__global__ void __launch_bounds__(128)
k_quant(const float* __restrict__ bias, float* __restrict__ out) {
    const int tid  = threadIdx.x;
    const int lane = tid & 31;
    const int wid  = tid >> 5;
    const int l    = blockIdx.x;
    const int j0   = wid * 9;

    const longlong2* bp =
        (const longlong2*)(g_part + (size_t)l * 4608) + lane;

    __shared__ longlong2 s[4][32];

    longlong2 pv[9];
    u64 t0 = 0ull, t1 = 0ull;
#pragma unroll
    for (int j = 0; j < 9; ++j) {
        pv[j] = bp[(j0 + j) * 32];
        t0 = add2(t0, (u64)pv[j].x);
        t1 = add2(t1, (u64)pv[j].y);
    }
    s[wid][lane] = make_longlong2((long long)t0, (long long)t1);
    __syncthreads();

    longlong2 bb = ((const longlong2*)bias)[lane];
    u64 tot0 = (u64)bb.x, tot1 = (u64)bb.y;
#pragma unroll
    for (int w2 = 0; w2 < 4; ++w2) {
        longlong2 v = s[w2][lane];
        tot0 = add2(tot0, (u64)v.x);
        tot1 = add2(tot1, (u64)v.y);
    }
    float2 f0 = unpack2(tot0), f1 = unpack2(tot1);
    float mx = fmaxf(fmaxf(f0.x, f0.y), fmaxf(f1.x, f1.y));
    float mn = fminf(fminf(f0.x, f0.y), fminf(f1.x, f1.y));
#pragma unroll
    for (int sft = 16; sft > 0; sft >>= 1) {
        mx = fmaxf(mx, __shfl_xor_sync(0xffffffffu, mx, sft));
        mn = fminf(mn, __shfl_xor_sync(0xffffffffu, mn, sft));
    }

    const float sc = (mx - mn) * (1.0f / 255.0f);
    float z = -mn / sc;                              // inf/nan if sc==0
    z = fminf(fmaxf(z, 0.0f), 255.0f);               // clip (nan -> 0)
    if (isnan(z)) z = 0.0f;
    const float zp  = truncf(z);                     // .int() truncation
    const float rcp = 1.0f / sc;

    const float MAGIC = 12582912.0f;                 // 1.5 * 2^23
    const u64 rcp2 = bcast2(rcp);
    const u64 mg2  = bcast2(MAGIC);
    const u64 zm2  = bcast2(zp - MAGIC);

    float ox = 0.f, oy = 0.f, oz = 0.f, ow = 0.f;
#pragma unroll
    for (int j = 0; j < 9; ++j) {
        u64 r0 = add2(fma2((u64)pv[j].x, rcp2, mg2), zm2);  // rint(v/sc)+zp
        u64 r1 = add2(fma2((u64)pv[j].y, rcp2, mg2), zm2);
        float2 c0 = unpack2(r0), c1 = unpack2(r1);
        ox += fminf(fmaxf(c0.x, 0.0f), 255.0f);
        oy += fminf(fmaxf(c0.y, 0.0f), 255.0f);
        oz += fminf(fmaxf(c1.x, 0.0f), 255.0f);
        ow += fminf(fmaxf(c1.y, 0.0f), 255.0f);
    }
    __syncthreads();
    s[wid][lane] = make_longlong2((long long)pack2(ox, oy),
                                  (long long)pack2(oz, ow));
    __syncthreads();

    const float* sf = (const float*)s;               // [warp][128 oc]
    float v = sf[tid] + sf[128 + tid] + sf[256 + tid] + sf[384 + tid];
    out[(tid << 10) + l] = (v - 36.0f * zp) * sc;
}

// ---------------------------------------------------------------------------
extern "C" void kernel_launch(void* const* d_in, const int* in_sizes, int n_in,
                              void* d_out, int out_size) {
    const float *x = nullptr, *w = nullptr, *b = nullptr;
    for (int i = 0; i < n_in; ++i) {
        if      (in_sizes[i] == 131072) x = (const float*)d_in[i];  // 128*32*32
        else if (in_sizes[i] == 147456) w = (const float*)d_in[i];  // 128*128*9
        else if (in_sizes[i] == 128)    b = (const float*)d_in[i];
    }
    k_partials<<<dim3(8, 36), 256>>>(x, w);
    k_quant<<<1024, 128>>>(b, (float*)d_out);
}